// round 5
// baseline (speedup 1.0000x reference)
#include <cuda_runtime.h>
#include <math.h>

// FFM forward, two-phase to give each gather stream exclusive L2:
//   K1: field 2 (50-step, 160MB table) -> v2, feat2 into __device__ scratch
//   K2: fields 0,1,3,4,5 (E3's 32MB table now L2-resident) + combine + sigmoid

#define WPB   8
#define BATCH 16384

__device__ __align__(16) float g_v2[BATCH * 80];   // 5 slots x 16
__device__ float g_feat2[BATCH];

__constant__ int c_pair_i[15] = {0,0,0,0,0,1,1,1,1,2,2,2,3,3,4};
__constant__ int c_pair_j[15] = {1,2,3,4,5,2,3,4,5,3,4,5,4,5,5};

// ---------------- K1: field 2 ----------------
extern "C" __global__ void __launch_bounds__(WPB * 32)
ffm_field2_kernel(const int* __restrict__ x2,
                  const float* __restrict__ E2,
                  const float* __restrict__ L2)
{
    const int warp = threadIdx.x >> 5;
    const int lane = threadIdx.x & 31;
    const int b = blockIdx.x * WPB + warp;
    if (b >= BATCH) return;

    const int slot  = lane >> 2;  // 0..7, active <5
    const int chunk = lane & 3;

    const int* xb = x2 + (size_t)b * 50;
    const int i2a = __ldg(xb + lane);
    const int i2b = (lane < 18) ? __ldg(xb + 32 + lane) : 0;

    const float* base = E2 + (size_t)slot * 500000 * 16 + chunk * 4;

    float4 acc = make_float4(0.f, 0.f, 0.f, 0.f);
    float  lacc = 0.f;

#pragma unroll
    for (int s = 0; s < 50; ++s) {
        const int idx = (s < 32) ? __shfl_sync(0xffffffffu, i2a, s)
                                 : __shfl_sync(0xffffffffu, i2b, s - 32);
        if (lane < 20) {
            const float4 e = __ldg((const float4*)(base + (size_t)idx * 16));
            acc.x += e.x; acc.y += e.y; acc.z += e.z; acc.w += e.w;
        } else if (lane >= 24 && ((s & 7) == lane - 24)) {
            lacc += __ldg(L2 + idx);
        }
    }

    if (lane < 20) {
        float4 r = make_float4(acc.x * 0.02f, acc.y * 0.02f, acc.z * 0.02f, acc.w * 0.02f);
        ((float4*)(g_v2 + (size_t)b * 80))[lane] = r;
    }
    float p = (lane >= 24) ? lacc : 0.f;
#pragma unroll
    for (int off = 16; off; off >>= 1)
        p += __shfl_xor_sync(0xffffffffu, p, off);
    if (lane == 0) g_feat2[b] = p * 0.02f;
}

// ---------------- K2: remaining fields + combine ----------------
template<int SEQN>
__device__ __forceinline__ void process_field(
    const int* __restrict__ x, const float* __restrict__ E,
    const float* __restrict__ L, int dim, int b, int lane,
    float* __restrict__ v_field, float* __restrict__ feat)
{
    const int slot  = lane >> 2;
    const int chunk = lane & 3;
    float4 acc = make_float4(0.f, 0.f, 0.f, 0.f);
    float  lacc = 0.f;
    const int* xb = x + (size_t)b * SEQN;

#pragma unroll
    for (int s = 0; s < SEQN; ++s) {
        const int idx = __ldg(xb + s);
        if (lane < 20) {
            const float4 e = __ldg(reinterpret_cast<const float4*>(
                E + ((size_t)slot * dim + idx) * 16) + chunk);
            acc.x += e.x; acc.y += e.y; acc.z += e.z; acc.w += e.w;
        } else if (lane == 20) {
            lacc += __ldg(L + idx);
        }
    }
    const float inv = 1.0f / (float)SEQN;
    if (lane < 20) {
        float4 r = make_float4(acc.x * inv, acc.y * inv, acc.z * inv, acc.w * inv);
        *reinterpret_cast<float4*>(v_field + slot * 16 + chunk * 4) = r;
    } else if (lane == 20) {
        *feat = lacc * inv;
    }
}

extern "C" __global__ void __launch_bounds__(WPB * 32)
ffm_rest_kernel(const int* __restrict__ x0, const int* __restrict__ x1,
                const int* __restrict__ x3,
                const int* __restrict__ x4, const int* __restrict__ x5,
                const float* __restrict__ E0, const float* __restrict__ E1,
                const float* __restrict__ E3,
                const float* __restrict__ E4, const float* __restrict__ E5,
                const float* __restrict__ L0, const float* __restrict__ L1,
                const float* __restrict__ L3,
                const float* __restrict__ L4, const float* __restrict__ L5,
                const float* __restrict__ Wd, const float* __restrict__ bd,
                float* __restrict__ out)
{
    __shared__ __align__(16) float sv[WPB][6 * 80];
    __shared__ float sfeat[WPB][8];

    const int warp = threadIdx.x >> 5;
    const int lane = threadIdx.x & 31;
    const int b = blockIdx.x * WPB + warp;
    if (b >= BATCH) return;

    float* v    = sv[warp];
    float* feat = sfeat[warp];

    // heavy reused field first (E3 table L2-resident in this phase)
    process_field<20>(x3, E3, L3,  100000, b, lane, v + 3 * 80, feat + 3);
    process_field<1 >(x0, E0, L0, 1000000, b, lane, v + 0 * 80, feat + 0);
    process_field<1 >(x1, E1, L1,  500000, b, lane, v + 1 * 80, feat + 1);
    process_field<1 >(x4, E4, L4,   10000, b, lane, v + 4 * 80, feat + 4);
    process_field<1 >(x5, E5, L5,    1000, b, lane, v + 5 * 80, feat + 5);

    // field 2 results from scratch (coalesced)
    if (lane < 20)
        ((float4*)(v + 2 * 80))[lane] = ((const float4*)(g_v2 + (size_t)b * 80))[lane];
    else if (lane == 21)
        feat[2] = g_feat2[b];

    __syncwarp();

    float partial = 0.f;
#pragma unroll
    for (int r = 0; r < 2; ++r) {
        const int item = lane + r * 32;
        if (item < 60) {
            const int t = item >> 2;
            const int c = item & 3;
            const int i = c_pair_i[t];
            const int j = c_pair_j[t];
            const float4 a  = *(const float4*)(v + i * 80 + (j - 1) * 16 + c * 4);
            const float4 bb = *(const float4*)(v + j * 80 +  i      * 16 + c * 4);
            partial += a.x * bb.x + a.y * bb.y + a.z * bb.z + a.w * bb.w;
        }
    }
#pragma unroll
    for (int off = 16; off; off >>= 1)
        partial += __shfl_xor_sync(0xffffffffu, partial, off);

    if (lane == 0) {
        float lin = __ldg(bd);
#pragma unroll
        for (int i = 0; i < 6; ++i) lin += feat[i] * __ldg(Wd + i);
        lin = fmaxf(lin, 0.f);
        out[b] = 1.0f / (1.0f + expf(-(lin + partial)));
    }
}

extern "C" void kernel_launch(void* const* d_in, const int* in_sizes, int n_in,
                              void* d_out, int out_size)
{
    const int* xs[6];
    for (int i = 0; i < 6; ++i) xs[i] = (const int*)d_in[i];

    // Classify E/L by element count (robust to input ordering):
    // E_i has 80*DIM_i elements, L_i has DIM_i. Disjoint size sets.
    const float* E[6] = {0,0,0,0,0,0};
    const float* L[6] = {0,0,0,0,0,0};
    const float* Wd = 0;
    const float* bd = 0;
    int ei = 0, li = 0;
    for (int k = 6; k < n_in; ++k) {
        const long long sz = (long long)in_sizes[k];
        const float* p = (const float*)d_in[k];
        if (sz == 80000000LL || sz == 40000000LL || sz == 8000000LL ||
            sz == 800000LL   || sz == 80000LL) {
            if (ei < 6) E[ei++] = p;
        } else if (sz == 1000000LL || sz == 500000LL || sz == 100000LL ||
                   sz == 10000LL   || sz == 1000LL) {
            if (li < 6) L[li++] = p;
        } else if (sz == 6LL) {
            Wd = p;
        } else if (sz == 1LL) {
            bd = p;
        }
    }

    float* out = (float*)d_out;
    const int blocks = BATCH / WPB; // 2048

    // Phase 1: big streaming gather gets the L2 to itself.
    ffm_field2_kernel<<<blocks, WPB * 32>>>(xs[2], E[2], L[2]);
    // Phase 2: E3 (32MB, 3.3x reuse) now L2-resident; combine + output.
    ffm_rest_kernel<<<blocks, WPB * 32>>>(
        xs[0], xs[1], xs[3], xs[4], xs[5],
        E[0], E[1], E[3], E[4], E[5],
        L[0], L[1], L[3], L[4], L[5],
        Wd, bd, out);
}

// round 6
// speedup vs baseline: 1.7850x; 1.7850x over previous
#include <cuda_runtime.h>
#include <math.h>

// FFM forward, slot-major multi-kernel:
//  K1: E2 gather, slot-major (grid.y-ish phase per slot; 32MB subtable fits L2
//      so the ~2x re-draw reuse becomes L2 hits)              -> g_v2
//  K2: E3 gather, slot-major (6.4MB subtable, trivially resident) -> g_v3
//  K3: 1-step fields + L-table feats + pair dots + sigmoid

#define WPB   8
#define BATCH 16384

__device__ __align__(16) float g_v2[BATCH * 80];   // 5 slots x 16
__device__ __align__(16) float g_v3[BATCH * 80];

__constant__ int c_pair_i[15] = {0,0,0,0,0,1,1,1,1,2,2,2,3,3,4};
__constant__ int c_pair_j[15] = {1,2,3,4,5,2,3,4,5,3,4,5,4,5,5};

// One warp handles one (batch, slot). Lanes: dg = lane>>2 (8 draw groups),
// chunk = lane&3 (16B chunks of the 64B row). 8 rows in flight per iteration.
template<int SEQN>
__global__ void __launch_bounds__(WPB * 32)
ffm_slot_gather(const int* __restrict__ x, const float* __restrict__ E,
                float* __restrict__ vout, int dim, float inv)
{
    const int warp = threadIdx.x >> 5;
    const int lane = threadIdx.x & 31;
    const int bps  = gridDim.x / 5;          // blocks per slot phase
    const int slot = blockIdx.x / bps;       // x-fastest dispatch => slot phases
    const int bx   = blockIdx.x - slot * bps;
    const int b    = bx * WPB + warp;

    const int dg    = lane >> 2;
    const int chunk = lane & 3;

    int ia = 0, ib = 0;
    if (lane < (SEQN < 32 ? SEQN : 32)) ia = __ldg(x + (size_t)b * SEQN + lane);
    if (SEQN > 32 && lane < SEQN - 32)  ib = __ldg(x + (size_t)b * SEQN + 32 + lane);

    const float* base = E + (size_t)slot * dim * 16 + chunk * 4;
    float4 acc = make_float4(0.f, 0.f, 0.f, 0.f);

#pragma unroll
    for (int t = 0; t < (SEQN + 7) / 8; ++t) {
        const int d = t * 8 + dg;
        const int idx = (d < 32) ? __shfl_sync(0xffffffffu, ia, d)
                                 : __shfl_sync(0xffffffffu, ib, d - 32);
        if (d < SEQN) {
            const float4 e = __ldg((const float4*)(base + (size_t)idx * 16));
            acc.x += e.x; acc.y += e.y; acc.z += e.z; acc.w += e.w;
        }
    }
    // reduce over the 8 draw groups (lane bits 2..4)
#pragma unroll
    for (int off = 4; off <= 16; off <<= 1) {
        acc.x += __shfl_xor_sync(0xffffffffu, acc.x, off);
        acc.y += __shfl_xor_sync(0xffffffffu, acc.y, off);
        acc.z += __shfl_xor_sync(0xffffffffu, acc.z, off);
        acc.w += __shfl_xor_sync(0xffffffffu, acc.w, off);
    }
    if (lane < 4) {
        float4 r = make_float4(acc.x * inv, acc.y * inv, acc.z * inv, acc.w * inv);
        ((float4*)(vout + (size_t)b * 80 + slot * 16))[lane] = r;
    }
}

// ---------------- K3: 1-step fields + feats + combine ----------------
extern "C" __global__ void __launch_bounds__(WPB * 32)
ffm_combine(const int* __restrict__ x0, const int* __restrict__ x1,
            const int* __restrict__ x2, const int* __restrict__ x3,
            const int* __restrict__ x4, const int* __restrict__ x5,
            const float* __restrict__ E0, const float* __restrict__ E1,
            const float* __restrict__ E4, const float* __restrict__ E5,
            const float* __restrict__ L0, const float* __restrict__ L1,
            const float* __restrict__ L2, const float* __restrict__ L3,
            const float* __restrict__ L4, const float* __restrict__ L5,
            const float* __restrict__ Wd, const float* __restrict__ bd,
            float* __restrict__ out)
{
    __shared__ __align__(16) float sv[WPB][6 * 80];
    __shared__ float sfeat[WPB][8];

    const int warp = threadIdx.x >> 5;
    const int lane = threadIdx.x & 31;
    const int b = blockIdx.x * WPB + warp;
    if (b >= BATCH) return;

    float* v    = sv[warp];
    float* feat = sfeat[warp];

    const int slot  = lane >> 2;
    const int chunk = lane & 3;

    const int idx0 = __ldg(x0 + b);
    const int idx1 = __ldg(x1 + b);
    const int idx4 = __ldg(x4 + b);
    const int idx5 = __ldg(x5 + b);

    // 1-step embedding gathers (lanes 0..19)
    if (lane < 20) {
        const float4 e0 = __ldg((const float4*)(E0 + ((size_t)slot * 1000000 + idx0) * 16) + chunk);
        const float4 e1 = __ldg((const float4*)(E1 + ((size_t)slot * 500000  + idx1) * 16) + chunk);
        const float4 e4 = __ldg((const float4*)(E4 + ((size_t)slot * 10000   + idx4) * 16) + chunk);
        const float4 e5 = __ldg((const float4*)(E5 + ((size_t)slot * 1000    + idx5) * 16) + chunk);
        ((float4*)(v + 0 * 80))[lane] = e0;
        ((float4*)(v + 1 * 80))[lane] = e1;
        ((float4*)(v + 4 * 80))[lane] = e4;
        ((float4*)(v + 5 * 80))[lane] = e5;
        // v2 / v3 readback (coalesced 320B per warp)
        ((float4*)(v + 2 * 80))[lane] = ((const float4*)(g_v2 + (size_t)b * 80))[lane];
        ((float4*)(v + 3 * 80))[lane] = ((const float4*)(g_v3 + (size_t)b * 80))[lane];
    } else if (lane == 20) feat[0] = __ldg(L0 + idx0);
    else if (lane == 21)   feat[1] = __ldg(L1 + idx1);
    else if (lane == 22)   feat[4] = __ldg(L4 + idx4);
    else if (lane == 23)   feat[5] = __ldg(L5 + idx5);

    // L-table feats for multi-step fields (tables <= 4MB, L2-resident)
    const int i2a = __ldg(x2 + (size_t)b * 50 + lane);
    const int i2b = (lane < 18) ? __ldg(x2 + (size_t)b * 50 + 32 + lane) : 0;
    const int i3  = (lane < 20) ? __ldg(x3 + (size_t)b * 20 + lane) : 0;

    float p2 = __ldg(L2 + i2a) + ((lane < 18) ? __ldg(L2 + i2b) : 0.f);
    float p3 = (lane < 20) ? __ldg(L3 + i3) : 0.f;
#pragma unroll
    for (int off = 16; off; off >>= 1) {
        p2 += __shfl_xor_sync(0xffffffffu, p2, off);
        p3 += __shfl_xor_sync(0xffffffffu, p3, off);
    }
    if (lane == 0) { feat[2] = p2 * 0.02f; feat[3] = p3 * 0.05f; }
    __syncwarp();

    // pair interactions: 15 pairs x 4 chunks = 60 items
    float partial = 0.f;
#pragma unroll
    for (int r = 0; r < 2; ++r) {
        const int item = lane + r * 32;
        if (item < 60) {
            const int t = item >> 2;
            const int c = item & 3;
            const int i = c_pair_i[t];
            const int j = c_pair_j[t];
            const float4 a  = *(const float4*)(v + i * 80 + (j - 1) * 16 + c * 4);
            const float4 bb = *(const float4*)(v + j * 80 +  i      * 16 + c * 4);
            partial += a.x * bb.x + a.y * bb.y + a.z * bb.z + a.w * bb.w;
        }
    }
#pragma unroll
    for (int off = 16; off; off >>= 1)
        partial += __shfl_xor_sync(0xffffffffu, partial, off);

    if (lane == 0) {
        float lin = __ldg(bd);
#pragma unroll
        for (int i = 0; i < 6; ++i) lin += feat[i] * __ldg(Wd + i);
        lin = fmaxf(lin, 0.f);
        out[b] = 1.0f / (1.0f + expf(-(lin + partial)));
    }
}

extern "C" void kernel_launch(void* const* d_in, const int* in_sizes, int n_in,
                              void* d_out, int out_size)
{
    const int* xs[6];
    for (int i = 0; i < 6; ++i) xs[i] = (const int*)d_in[i];

    // Classify E/L by element count (robust to input ordering):
    // E_i has 80*DIM_i elements, L_i has DIM_i. Disjoint size sets.
    const float* E[6] = {0,0,0,0,0,0};
    const float* L[6] = {0,0,0,0,0,0};
    const float* Wd = 0;
    const float* bd = 0;
    int ei = 0, li = 0;
    for (int k = 6; k < n_in; ++k) {
        const long long sz = (long long)in_sizes[k];
        const float* p = (const float*)d_in[k];
        if (sz == 80000000LL || sz == 40000000LL || sz == 8000000LL ||
            sz == 800000LL   || sz == 80000LL) {
            if (ei < 6) E[ei++] = p;
        } else if (sz == 1000000LL || sz == 500000LL || sz == 100000LL ||
                   sz == 10000LL   || sz == 1000LL) {
            if (li < 6) L[li++] = p;
        } else if (sz == 6LL) {
            Wd = p;
        } else if (sz == 1LL) {
            bd = p;
        }
    }

    float* out = (float*)d_out;
    const int bps = BATCH / WPB;  // 2048 blocks per slot phase

    float* v2p; cudaGetSymbolAddress((void**)&v2p, g_v2);
    float* v3p; cudaGetSymbolAddress((void**)&v3p, g_v3);

    // K1: field 2, slot-major (5 phases of 2048 blocks)
    ffm_slot_gather<50><<<bps * 5, WPB * 32>>>(xs[2], E[2], v2p, 500000, 0.02f);
    // K2: field 3, slot-major
    ffm_slot_gather<20><<<bps * 5, WPB * 32>>>(xs[3], E[3], v3p, 100000, 0.05f);
    // K3: combine
    ffm_combine<<<bps, WPB * 32>>>(
        xs[0], xs[1], xs[2], xs[3], xs[4], xs[5],
        E[0], E[1], E[4], E[5],
        L[0], L[1], L[2], L[3], L[4], L[5],
        Wd, bd, out);
}

// round 7
// speedup vs baseline: 1.8853x; 1.0562x over previous
#include <cuda_runtime.h>
#include <math.h>

// FFM forward, slot-major fused gather + combine:
//  K1 (fused): field-3 slot phases (5 x 2048 blocks) then field-2 slot phases
//      (5 x 2048). Each slot's subtable (6.4MB / 32MB) fits L2, so re-drawn
//      rows hit L2. Single kernel => one launch gap instead of two.
//  K2: 1-step fields + L-table feats + pair dots + sigmoid.

#define WPB   8
#define BATCH 16384
#define BPS   (BATCH / WPB)   // 2048 blocks per slot phase

__device__ __align__(16) float g_v2[BATCH * 80];   // 5 slots x 16
__device__ __align__(16) float g_v3[BATCH * 80];

__constant__ int c_pair_i[15] = {0,0,0,0,0,1,1,1,1,2,2,2,3,3,4};
__constant__ int c_pair_j[15] = {1,2,3,4,5,2,3,4,5,3,4,5,4,5,5};

// One warp handles one (batch, slot). Lanes: dg = lane>>2 (8 draw groups),
// chunk = lane&3 (16B chunk of the 64B row). 8 rows in flight per iteration.
template<int SEQN>
__device__ __forceinline__ void slot_gather(
    const int* __restrict__ x, const float* __restrict__ E,
    float* __restrict__ vout, int dim, float inv, int slot, int bx,
    int warp, int lane)
{
    const int b = bx * WPB + warp;
    const int dg    = lane >> 2;
    const int chunk = lane & 3;

    int ia = 0, ib = 0;
    if (lane < (SEQN < 32 ? SEQN : 32)) ia = __ldg(x + (size_t)b * SEQN + lane);
    if (SEQN > 32 && lane < SEQN - 32)  ib = __ldg(x + (size_t)b * SEQN + 32 + lane);

    const float* base = E + (size_t)slot * dim * 16 + chunk * 4;
    float4 acc = make_float4(0.f, 0.f, 0.f, 0.f);

#pragma unroll
    for (int t = 0; t < (SEQN + 7) / 8; ++t) {
        const int d = t * 8 + dg;
        const int idx = (d < 32) ? __shfl_sync(0xffffffffu, ia, d)
                                 : __shfl_sync(0xffffffffu, ib, d - 32);
        if (d < SEQN) {
            const float4 e = __ldg((const float4*)(base + (size_t)idx * 16));
            acc.x += e.x; acc.y += e.y; acc.z += e.z; acc.w += e.w;
        }
    }
#pragma unroll
    for (int off = 4; off <= 16; off <<= 1) {
        acc.x += __shfl_xor_sync(0xffffffffu, acc.x, off);
        acc.y += __shfl_xor_sync(0xffffffffu, acc.y, off);
        acc.z += __shfl_xor_sync(0xffffffffu, acc.z, off);
        acc.w += __shfl_xor_sync(0xffffffffu, acc.w, off);
    }
    if (lane < 4) {
        float4 r = make_float4(acc.x * inv, acc.y * inv, acc.z * inv, acc.w * inv);
        ((float4*)(vout + (size_t)b * 80 + slot * 16))[lane] = r;
    }
}

extern "C" __global__ void __launch_bounds__(WPB * 32)
ffm_gather_fused(const int* __restrict__ x2, const float* __restrict__ E2,
                 const int* __restrict__ x3, const float* __restrict__ E3,
                 float* __restrict__ v2, float* __restrict__ v3)
{
    const int warp = threadIdx.x >> 5;
    const int lane = threadIdx.x & 31;

    int bid = blockIdx.x;
    if (bid < 5 * BPS) {
        // field 3 first (small, fills the launch ramp)
        const int slot = bid / BPS;
        const int bx   = bid - slot * BPS;
        slot_gather<20>(x3, E3, v3, 100000, 0.05f, slot, bx, warp, lane);
    } else {
        bid -= 5 * BPS;
        const int slot = bid / BPS;
        const int bx   = bid - slot * BPS;
        slot_gather<50>(x2, E2, v2, 500000, 0.02f, slot, bx, warp, lane);
    }
}

// ---------------- K2: 1-step fields + feats + combine ----------------
extern "C" __global__ void __launch_bounds__(WPB * 32)
ffm_combine(const int* __restrict__ x0, const int* __restrict__ x1,
            const int* __restrict__ x2, const int* __restrict__ x3,
            const int* __restrict__ x4, const int* __restrict__ x5,
            const float* __restrict__ E0, const float* __restrict__ E1,
            const float* __restrict__ E4, const float* __restrict__ E5,
            const float* __restrict__ L0, const float* __restrict__ L1,
            const float* __restrict__ L2, const float* __restrict__ L3,
            const float* __restrict__ L4, const float* __restrict__ L5,
            const float* __restrict__ Wd, const float* __restrict__ bd,
            float* __restrict__ out)
{
    __shared__ __align__(16) float sv[WPB][6 * 80];
    __shared__ float sfeat[WPB][8];

    const int warp = threadIdx.x >> 5;
    const int lane = threadIdx.x & 31;
    const int b = blockIdx.x * WPB + warp;
    if (b >= BATCH) return;

    float* v    = sv[warp];
    float* feat = sfeat[warp];

    const int slot  = lane >> 2;
    const int chunk = lane & 3;

    // All independent index loads issued up front.
    const int idx0 = __ldg(x0 + b);
    const int idx1 = __ldg(x1 + b);
    const int idx4 = __ldg(x4 + b);
    const int idx5 = __ldg(x5 + b);
    const int i2a  = __ldg(x2 + (size_t)b * 50 + lane);
    const int i2b  = (lane < 18) ? __ldg(x2 + (size_t)b * 50 + 32 + lane) : 0;
    const int i3   = (lane < 20) ? __ldg(x3 + (size_t)b * 20 + lane) : 0;

    // L-table gathers (tables <= 4MB, L2-resident) — independent of smem work
    float p2 = __ldg(L2 + i2a) + ((lane < 18) ? __ldg(L2 + i2b) : 0.f);
    float p3 = (lane < 20) ? __ldg(L3 + i3) : 0.f;

    if (lane < 20) {
        const float4 e0 = __ldg((const float4*)(E0 + ((size_t)slot * 1000000 + idx0) * 16) + chunk);
        const float4 e1 = __ldg((const float4*)(E1 + ((size_t)slot * 500000  + idx1) * 16) + chunk);
        const float4 e4 = __ldg((const float4*)(E4 + ((size_t)slot * 10000   + idx4) * 16) + chunk);
        const float4 e5 = __ldg((const float4*)(E5 + ((size_t)slot * 1000    + idx5) * 16) + chunk);
        const float4 w2 = ((const float4*)(g_v2 + (size_t)b * 80))[lane];
        const float4 w3 = ((const float4*)(g_v3 + (size_t)b * 80))[lane];
        ((float4*)(v + 0 * 80))[lane] = e0;
        ((float4*)(v + 1 * 80))[lane] = e1;
        ((float4*)(v + 4 * 80))[lane] = e4;
        ((float4*)(v + 5 * 80))[lane] = e5;
        ((float4*)(v + 2 * 80))[lane] = w2;
        ((float4*)(v + 3 * 80))[lane] = w3;
    } else if (lane == 20) feat[0] = __ldg(L0 + idx0);
    else if (lane == 21)   feat[1] = __ldg(L1 + idx1);
    else if (lane == 22)   feat[4] = __ldg(L4 + idx4);
    else if (lane == 23)   feat[5] = __ldg(L5 + idx5);

#pragma unroll
    for (int off = 16; off; off >>= 1) {
        p2 += __shfl_xor_sync(0xffffffffu, p2, off);
        p3 += __shfl_xor_sync(0xffffffffu, p3, off);
    }
    if (lane == 0) { feat[2] = p2 * 0.02f; feat[3] = p3 * 0.05f; }
    __syncwarp();

    // pair interactions: 15 pairs x 4 chunks = 60 items
    float partial = 0.f;
#pragma unroll
    for (int r = 0; r < 2; ++r) {
        const int item = lane + r * 32;
        if (item < 60) {
            const int t = item >> 2;
            const int c = item & 3;
            const int i = c_pair_i[t];
            const int j = c_pair_j[t];
            const float4 a  = *(const float4*)(v + i * 80 + (j - 1) * 16 + c * 4);
            const float4 bb = *(const float4*)(v + j * 80 +  i      * 16 + c * 4);
            partial += a.x * bb.x + a.y * bb.y + a.z * bb.z + a.w * bb.w;
        }
    }
#pragma unroll
    for (int off = 16; off; off >>= 1)
        partial += __shfl_xor_sync(0xffffffffu, partial, off);

    if (lane == 0) {
        float lin = __ldg(bd);
#pragma unroll
        for (int i = 0; i < 6; ++i) lin += feat[i] * __ldg(Wd + i);
        lin = fmaxf(lin, 0.f);
        out[b] = 1.0f / (1.0f + expf(-(lin + partial)));
    }
}

extern "C" void kernel_launch(void* const* d_in, const int* in_sizes, int n_in,
                              void* d_out, int out_size)
{
    const int* xs[6];
    for (int i = 0; i < 6; ++i) xs[i] = (const int*)d_in[i];

    // Classify E/L by element count (robust to input ordering):
    // E_i has 80*DIM_i elements, L_i has DIM_i. Disjoint size sets.
    const float* E[6] = {0,0,0,0,0,0};
    const float* L[6] = {0,0,0,0,0,0};
    const float* Wd = 0;
    const float* bd = 0;
    int ei = 0, li = 0;
    for (int k = 6; k < n_in; ++k) {
        const long long sz = (long long)in_sizes[k];
        const float* p = (const float*)d_in[k];
        if (sz == 80000000LL || sz == 40000000LL || sz == 8000000LL ||
            sz == 800000LL   || sz == 80000LL) {
            if (ei < 6) E[ei++] = p;
        } else if (sz == 1000000LL || sz == 500000LL || sz == 100000LL ||
                   sz == 10000LL   || sz == 1000LL) {
            if (li < 6) L[li++] = p;
        } else if (sz == 6LL) {
            Wd = p;
        } else if (sz == 1LL) {
            bd = p;
        }
    }

    float* out = (float*)d_out;

    float* v2p; cudaGetSymbolAddress((void**)&v2p, g_v2);
    float* v3p; cudaGetSymbolAddress((void**)&v3p, g_v3);

    // K1: fused slot-major gathers (field 3 phases, then field 2 phases)
    ffm_gather_fused<<<BPS * 10, WPB * 32>>>(xs[2], E[2], xs[3], E[3], v2p, v3p);
    // K2: combine
    ffm_combine<<<BPS, WPB * 32>>>(
        xs[0], xs[1], xs[2], xs[3], xs[4], xs[5],
        E[0], E[1], E[4], E[5],
        L[0], L[1], L[2], L[3], L[4], L[5],
        Wd, bd, out);
}